// round 1
// baseline (speedup 1.0000x reference)
#include <cuda_runtime.h>

// Live computation (GNN branch in the reference is dead code — its output is
// overwritten by static_feature before the FC stack):
//   h1 = relu(sf @ Wfc1^T + bfc1)     [N,12] -> [N,64]
//   h2 = relu(h1 @ Wfc2^T + bfc2)     [N,64] -> [N,64]
//   out = h2 @ Wp^T + bp              [N,64] -> [N,1]
//
// Input order (metadata):
//  0: x            [100000,27]  (unused)
//  1: edge_index   [2,3200000] int64 (unused)
//  2: static_feature [100000,12]
//  3: W1l, 4: b1, 5: W1r, 6: W2l, 7: b2, 8: W2r   (unused)
//  9: Wfc1 [64,12], 10: bfc1 [64], 11: Wfc2 [64,64], 12: bfc2 [64],
// 13: Wp [1,64], 14: bp [1]

#define NN   100000
#define SF   12
#define FC   64
#define TPB  256

__global__ __launch_bounds__(TPB)
void fused_mlp_kernel(const float* __restrict__ sf,
                      const float* __restrict__ W1, const float* __restrict__ b1,
                      const float* __restrict__ W2, const float* __restrict__ b2,
                      const float* __restrict__ Wp, const float* __restrict__ bp,
                      float* __restrict__ out)
{
    __shared__ __align__(16) float sW1[FC * SF];   // 3 KB
    __shared__ __align__(16) float sW2[FC * FC];   // 16 KB
    __shared__ float sb1[FC];
    __shared__ float sb2[FC];
    __shared__ float sWp[FC];
    __shared__ float sbp;

    const int tid = threadIdx.x;
    for (int i = tid; i < FC * SF; i += TPB) sW1[i] = W1[i];
    for (int i = tid; i < FC * FC; i += TPB) sW2[i] = W2[i];
    if (tid < FC) { sb1[tid] = b1[tid]; sb2[tid] = b2[tid]; sWp[tid] = Wp[tid]; }
    if (tid == 0) sbp = bp[0];
    __syncthreads();

    const int node = blockIdx.x * TPB + tid;
    if (node >= NN) return;

    // Load the 12 static features (row is 48 B, 16 B aligned -> 3x float4).
    float s[SF];
    const float4* sp = reinterpret_cast<const float4*>(sf + (size_t)node * SF);
    {
        float4 v0 = sp[0], v1 = sp[1], v2 = sp[2];
        s[0] = v0.x;  s[1] = v0.y;  s[2]  = v0.z;  s[3]  = v0.w;
        s[4] = v1.x;  s[5] = v1.y;  s[6]  = v1.z;  s[7]  = v1.w;
        s[8] = v2.x;  s[9] = v2.y;  s[10] = v2.z;  s[11] = v2.w;
    }

    // Layer 1: h1[i] = relu(b1[i] + sum_k W1[i][k] * s[k])
    float h1[FC];
    #pragma unroll
    for (int i = 0; i < FC; i++) {
        float t = sb1[i];
        #pragma unroll
        for (int k = 0; k < SF; k += 4) {
            float4 w = *reinterpret_cast<const float4*>(&sW1[i * SF + k]);
            t = fmaf(w.x, s[k],     t);
            t = fmaf(w.y, s[k + 1], t);
            t = fmaf(w.z, s[k + 2], t);
            t = fmaf(w.w, s[k + 3], t);
        }
        h1[i] = fmaxf(t, 0.0f);
    }

    // Layer 2 fused with projection: acc = bp + sum_j Wp[j] * relu(b2[j] + W2[j]·h1)
    // Only one live accumulator beyond h1 -> keeps register pressure low.
    float acc = sbp;
    #pragma unroll 4
    for (int j = 0; j < FC; j++) {
        float t = sb2[j];
        #pragma unroll
        for (int k = 0; k < FC; k += 4) {
            float4 w = *reinterpret_cast<const float4*>(&sW2[j * FC + k]);
            t = fmaf(w.x, h1[k],     t);
            t = fmaf(w.y, h1[k + 1], t);
            t = fmaf(w.z, h1[k + 2], t);
            t = fmaf(w.w, h1[k + 3], t);
        }
        acc = fmaf(sWp[j], fmaxf(t, 0.0f), acc);
    }

    out[node] = acc;
}

extern "C" void kernel_launch(void* const* d_in, const int* in_sizes, int n_in,
                              void* d_out, int out_size)
{
    const float* sf = (const float*)d_in[2];
    const float* W1 = (const float*)d_in[9];
    const float* b1 = (const float*)d_in[10];
    const float* W2 = (const float*)d_in[11];
    const float* b2 = (const float*)d_in[12];
    const float* Wp = (const float*)d_in[13];
    const float* bp = (const float*)d_in[14];
    float* out = (float*)d_out;

    const int grid = (NN + TPB - 1) / TPB;   // 391
    fused_mlp_kernel<<<grid, TPB>>>(sf, W1, b1, W2, b2, Wp, bp, out);
}

// round 2
// speedup vs baseline: 1.0731x; 1.0731x over previous
#include <cuda_runtime.h>
#include <cstdint>

// Live computation (GNN branch is dead code in the reference):
//   h1 = relu(sf @ Wfc1^T + bfc1)     [N,12] -> [N,64]
//   h2 = relu(h1 @ Wfc2^T + bfc2)     [N,64] -> [N,64]
//   out = h2 @ Wp^T + bp              [N,64] -> [N,1]
//
// Strategy: one thread per node. All math through packed fma.rn.f32x2
// (2 fp32 MACs per issued instruction, bit-identical per lane to scalar FFMA).
// 4 independent packed accumulators per output break the FMA dependency chain.
// __launch_bounds__(128,4) caps registers at 128 -> 16 warps/SM.

#define NN   100000
#define SF   12
#define FC   64
#define TPB  128

using u64 = unsigned long long;

__device__ __forceinline__ u64 ffma2(u64 a, u64 b, u64 c) {
    u64 d;
    asm("fma.rn.f32x2 %0, %1, %2, %3;" : "=l"(d) : "l"(a), "l"(b), "l"(c));
    return d;
}
__device__ __forceinline__ u64 fadd2(u64 a, u64 b) {
    u64 d;
    asm("add.rn.f32x2 %0, %1, %2;" : "=l"(d) : "l"(a), "l"(b));
    return d;
}
__device__ __forceinline__ float hadd2(u64 v) {
    float lo, hi;
    asm("mov.b64 {%0,%1}, %2;" : "=f"(lo), "=f"(hi) : "l"(v));
    return lo + hi;
}
__device__ __forceinline__ u64 pack2(float lo, float hi) {
    u64 d;
    asm("mov.b64 %0, {%1,%2};" : "=l"(d) : "f"(lo), "f"(hi));
    return d;
}

__global__ __launch_bounds__(TPB, 4)
void fused_mlp_kernel(const float* __restrict__ sf,
                      const float* __restrict__ W1, const float* __restrict__ b1,
                      const float* __restrict__ W2, const float* __restrict__ b2,
                      const float* __restrict__ Wp, const float* __restrict__ bp,
                      float* __restrict__ out)
{
    // Weight rows stored as packed f32 pairs: identical memory layout to the
    // plain float arrays (pair p of row j = (w[2p], w[2p+1])).
    __shared__ __align__(16) u64 sW1[FC * SF / 2];   // 64 rows x 6 pairs  (3 KB)
    __shared__ __align__(16) u64 sW2[FC * FC / 2];   // 64 rows x 32 pairs (16 KB)
    __shared__ float sb1[FC];
    __shared__ float sb2[FC];
    __shared__ float sWp[FC];
    __shared__ float sbp;

    const int tid = threadIdx.x;
    {
        const u64* gW1 = reinterpret_cast<const u64*>(W1);
        const u64* gW2 = reinterpret_cast<const u64*>(W2);
        for (int i = tid; i < FC * SF / 2; i += TPB) sW1[i] = gW1[i];
        for (int i = tid; i < FC * FC / 2; i += TPB) sW2[i] = gW2[i];
        if (tid < FC) { sb1[tid] = b1[tid]; sb2[tid] = b2[tid]; sWp[tid] = Wp[tid]; }
        if (tid == 0) sbp = bp[0];
    }
    __syncthreads();

    const int node = blockIdx.x * TPB + tid;
    if (node >= NN) return;

    // 12 static features as 6 packed pairs (row = 48B, 16B-aligned).
    u64 s[SF / 2];
    {
        const ulonglong2* sp = reinterpret_cast<const ulonglong2*>(sf + (size_t)node * SF);
        ulonglong2 v0 = sp[0], v1 = sp[1], v2 = sp[2];
        s[0] = v0.x; s[1] = v0.y; s[2] = v1.x; s[3] = v1.y; s[4] = v2.x; s[5] = v2.y;
    }

    // ---- Layer 1: h1[i] = relu(b1[i] + W1[i]·s), packed pairwise dot ----
    // Produce h1 directly as 32 packed pairs (h1[2p], h1[2p+1]).
    u64 h1[FC / 2];
    #pragma unroll
    for (int p = 0; p < FC / 2; p++) {
        const int i0 = 2 * p, i1 = 2 * p + 1;
        u64 a0 = 0, a1 = 0, b0 = 0, b1_ = 0;
        #pragma unroll
        for (int k = 0; k < SF / 2; k += 2) {
            a0 = ffma2(sW1[i0 * (SF / 2) + k],     s[k],     a0);
            b0 = ffma2(sW1[i0 * (SF / 2) + k + 1], s[k + 1], b0);
            a1 = ffma2(sW1[i1 * (SF / 2) + k],     s[k],     a1);
            b1_ = ffma2(sW1[i1 * (SF / 2) + k + 1], s[k + 1], b1_);
        }
        float t0 = fmaxf(hadd2(fadd2(a0, b0)) + sb1[i0], 0.0f);
        float t1 = fmaxf(hadd2(fadd2(a1, b1_)) + sb1[i1], 0.0f);
        h1[p] = pack2(t0, t1);
    }

    // ---- Layer 2 fused with projection ----
    // acc = bp + sum_j Wp[j] * relu(b2[j] + W2[j]·h1)
    // 4 independent packed accumulators per j -> dep chain of 8, not 64.
    float acc = sbp;
    #pragma unroll 2
    for (int j = 0; j < FC; j++) {
        const u64* row = &sW2[j * (FC / 2)];
        u64 a0 = 0, a1 = 0, a2 = 0, a3 = 0;
        #pragma unroll
        for (int k = 0; k < FC / 2; k += 4) {
            a0 = ffma2(row[k],     h1[k],     a0);
            a1 = ffma2(row[k + 1], h1[k + 1], a1);
            a2 = ffma2(row[k + 2], h1[k + 2], a2);
            a3 = ffma2(row[k + 3], h1[k + 3], a3);
        }
        float t = hadd2(fadd2(fadd2(a0, a1), fadd2(a2, a3))) + sb2[j];
        acc = fmaf(sWp[j], fmaxf(t, 0.0f), acc);
    }

    out[node] = acc;
}

extern "C" void kernel_launch(void* const* d_in, const int* in_sizes, int n_in,
                              void* d_out, int out_size)
{
    const float* sf = (const float*)d_in[2];
    const float* W1 = (const float*)d_in[9];
    const float* b1 = (const float*)d_in[10];
    const float* W2 = (const float*)d_in[11];
    const float* b2 = (const float*)d_in[12];
    const float* Wp = (const float*)d_in[13];
    const float* bp = (const float*)d_in[14];
    float* out = (float*)d_out;

    const int grid = (NN + TPB - 1) / TPB;   // 782
    fused_mlp_kernel<<<grid, TPB>>>(sf, W1, b1, W2, b2, Wp, bp, out);
}

// round 3
// speedup vs baseline: 1.4016x; 1.3060x over previous
#include <cuda_runtime.h>
#include <cstdint>

// Live computation (GNN branch is dead code in the reference):
//   h1 = relu(sf @ Wfc1^T + bfc1)     [N,12] -> [N,64]
//   h2 = relu(h1 @ Wfc2^T + bfc2)     [N,64] -> [N,64]
//   out = h2 @ Wp^T + bp              [N,64] -> [N,1]
//
// Structure: register-blocked GEMM for layer 2 (the 83%-of-FLOPs part).
// Block = 128 threads -> 64-node x 64-output tile. Thread tile 8x4.
// All math via packed fma.rn.f32x2 with k-pair packing (loads land in u64
// registers directly from LDS.128 -> zero packing MOVs).

#define NN    100000
#define SF    12
#define FC    64
#define TPB   128
#define NPB   64          // nodes per block
#define PAD   68          // padded row length (floats) for sh1 / sW2
#define RPAD  17          // padded row for reduction buffer

using u64 = unsigned long long;

__device__ __forceinline__ u64 ffma2(u64 a, u64 b, u64 c) {
    u64 d;
    asm("fma.rn.f32x2 %0, %1, %2, %3;" : "=l"(d) : "l"(a), "l"(b), "l"(c));
    return d;
}
__device__ __forceinline__ u64 fadd2(u64 a, u64 b) {
    u64 d;
    asm("add.rn.f32x2 %0, %1, %2;" : "=l"(d) : "l"(a), "l"(b));
    return d;
}
__device__ __forceinline__ float hadd2(u64 v) {
    float lo, hi;
    asm("mov.b64 {%0,%1}, %2;" : "=f"(lo), "=f"(hi) : "l"(v));
    return lo + hi;
}

__global__ __launch_bounds__(TPB, 4)
void fused_mlp_kernel(const float* __restrict__ sf,
                      const float* __restrict__ W1, const float* __restrict__ b1,
                      const float* __restrict__ W2, const float* __restrict__ b2,
                      const float* __restrict__ Wp, const float* __restrict__ bp,
                      float* __restrict__ out)
{
    __shared__ __align__(16) u64   sW1[FC * SF / 2];      // 3 KB  (rows of W1 as f32 pairs)
    __shared__ __align__(16) float sW2p[FC * PAD];        // 17.4 KB (W2 rows, padded)
    __shared__ __align__(16) float sh1[NPB * PAD];        // 17.4 KB (h1 rows, padded)
    __shared__ float sred[NPB * RPAD];                    // 4.3 KB reduction buffer
    __shared__ float sb1[FC], sb2[FC], sWp[FC];
    __shared__ float sbp;

    const int tid = threadIdx.x;

    // ---- Stage weights ----
    {
        const u64* gW1 = reinterpret_cast<const u64*>(W1);
        for (int i = tid; i < FC * SF / 2; i += TPB) sW1[i] = gW1[i];
        for (int i = tid; i < FC * FC; i += TPB) {
            int j = i >> 6, k = i & 63;
            sW2p[j * PAD + k] = W2[i];
        }
        if (tid < FC) { sb1[tid] = b1[tid]; sb2[tid] = b2[tid]; sWp[tid] = Wp[tid]; }
        if (tid == 0) sbp = bp[0];
    }

    // ================= Phase A: h1 for 64 nodes =================
    // thread t: node = t%64, computes output half j in [32*(t/64), +32).
    {
        const int nloc = tid & 63;
        const int half = tid >> 6;          // 0 or 1
        const int node = blockIdx.x * NPB + nloc;

        u64 s[SF / 2];
        if (node < NN) {
            const ulonglong2* sp = reinterpret_cast<const ulonglong2*>(sf + (size_t)node * SF);
            ulonglong2 v0 = sp[0], v1 = sp[1], v2 = sp[2];
            s[0] = v0.x; s[1] = v0.y; s[2] = v1.x; s[3] = v1.y; s[4] = v2.x; s[5] = v2.y;
        } else {
            #pragma unroll
            for (int i = 0; i < SF / 2; i++) s[i] = 0ull;
        }
        __syncthreads();   // weights staged

        float* row = &sh1[nloc * PAD + half * 32];
        #pragma unroll
        for (int p = 0; p < 16; p++) {
            const int i0 = half * 32 + 2 * p, i1 = i0 + 1;
            u64 a0 = 0, b0 = 0, a1 = 0, c1 = 0;
            #pragma unroll
            for (int k = 0; k < SF / 2; k += 2) {
                a0 = ffma2(sW1[i0 * (SF / 2) + k],     s[k],     a0);
                b0 = ffma2(sW1[i0 * (SF / 2) + k + 1], s[k + 1], b0);
                a1 = ffma2(sW1[i1 * (SF / 2) + k],     s[k],     a1);
                c1 = ffma2(sW1[i1 * (SF / 2) + k + 1], s[k + 1], c1);
            }
            row[2 * p]     = fmaxf(hadd2(fadd2(a0, b0)) + sb1[i0], 0.0f);
            row[2 * p + 1] = fmaxf(hadd2(fadd2(a1, c1)) + sb1[i1], 0.0f);
        }
    }
    __syncthreads();

    // ================= Phase B: layer-2 GEMM =================
    // thread (nt = tid&7, ot = tid>>3): 8 nodes {nt+8i} x 4 outputs {4ot+jj}.
    const int nt = tid & 7;
    const int ot = tid >> 3;     // 0..15

    u64 acc[8][4];
    #pragma unroll
    for (int i = 0; i < 8; i++)
        #pragma unroll
        for (int j = 0; j < 4; j++) acc[i][j] = 0ull;

    #pragma unroll 4
    for (int k = 0; k < FC; k += 4) {
        // B fragment: 4 output rows, k..k+3 -> packed (k,k+1),(k+2,k+3)
        ulonglong2 bv[4];
        #pragma unroll
        for (int jj = 0; jj < 4; jj++)
            bv[jj] = *reinterpret_cast<const ulonglong2*>(&sW2p[(ot * 4 + jj) * PAD + k]);
        // A fragments: 8 nodes
        #pragma unroll
        for (int i = 0; i < 8; i++) {
            ulonglong2 av = *reinterpret_cast<const ulonglong2*>(&sh1[(nt + 8 * i) * PAD + k]);
            #pragma unroll
            for (int jj = 0; jj < 4; jj++) {
                acc[i][jj] = ffma2(av.x, bv[jj].x, acc[i][jj]);
                acc[i][jj] = ffma2(av.y, bv[jj].y, acc[i][jj]);
            }
        }
    }

    // ================= Phase C: relu + projection + reduce =================
    {
        float partial[8];
        #pragma unroll
        for (int i = 0; i < 8; i++) partial[i] = 0.0f;
        #pragma unroll
        for (int jj = 0; jj < 4; jj++) {
            const int j = ot * 4 + jj;
            const float bj = sb2[j], wj = sWp[j];
            #pragma unroll
            for (int i = 0; i < 8; i++) {
                float v = hadd2(acc[i][jj]) + bj;
                partial[i] = fmaf(wj, fmaxf(v, 0.0f), partial[i]);
            }
        }
        #pragma unroll
        for (int i = 0; i < 8; i++)
            sred[(nt + 8 * i) * RPAD + ot] = partial[i];
    }
    __syncthreads();

    if (tid < NPB) {
        const int node = blockIdx.x * NPB + tid;
        if (node < NN) {
            float sum = sbp;
            const float* r = &sred[tid * RPAD];
            #pragma unroll
            for (int o = 0; o < 16; o++) sum += r[o];
            out[node] = sum;
        }
    }
}

extern "C" void kernel_launch(void* const* d_in, const int* in_sizes, int n_in,
                              void* d_out, int out_size)
{
    const float* sf = (const float*)d_in[2];
    const float* W1 = (const float*)d_in[9];
    const float* b1 = (const float*)d_in[10];
    const float* W2 = (const float*)d_in[11];
    const float* b2 = (const float*)d_in[12];
    const float* Wp = (const float*)d_in[13];
    const float* bp = (const float*)d_in[14];
    float* out = (float*)d_out;

    const int grid = (NN + NPB - 1) / NPB;   // 1563
    fused_mlp_kernel<<<grid, TPB>>>(sf, W1, b1, W2, b2, Wp, bp, out);
}

// round 5
// speedup vs baseline: 2.0397x; 1.4553x over previous
#include <cuda_runtime.h>
#include <cuda_bf16.h>
#include <cstdint>

// Live computation (GNN branch is dead code in the reference):
//   h1 = relu(sf @ Wfc1^T + bfc1)     [N,12] -> [N,64]   (packed fp32 ffma2)
//   h2 = relu(h1 @ Wfc2^T + bfc2)     [N,64] -> [N,64]   (warp mma.sync bf16-split)
//   out = h2 @ Wp^T + bp              [N,64] -> [N,1]    (register epilogue)
//
// NOTE: harness compiles for plain sm_100 (no 'a') -> tcgen05 unavailable.
// mma.sync / ldmatrix are sm_80+ baseline features and legal here.
//
// bf16 split: x = hi(x) + lo(x - hi(x)); D = Ah*Bh + Al*Bh + Ah*Bl in fp32.
// Dropped Al*Bl term ~2^-16 relative; rel_err ~1e-5 << 1e-3 threshold.

#define NN    100000
#define SF    12
#define FC    64
#define TPB   128
#define NPB   128
#define STRIDE 144            // bytes per bf16 row (128 data + 16 pad)

using u64 = unsigned long long;

// ---- dynamic smem layout (byte offsets) ----
#define OFF_AH   0            // 128 x 144 B  (h1 hi)
#define OFF_AL   18432        // 128 x 144 B  (h1 lo)
#define OFF_BH   36864        // 64 x 144 B   (W2 hi)
#define OFF_BL   46080        // 64 x 144 B   (W2 lo)
#define OFF_W1   55296        // u64[384]     (W1 as f32 pairs)
#define OFF_B1   58368        // float[64]
#define OFF_B2   58624        // float[64]
#define OFF_WP   58880        // float[64]
#define OFF_BP   59136        // float
#define SMEM_DYN 59392

__device__ __forceinline__ uint32_t smem_u32(const void* p) {
    uint32_t a;
    asm("{ .reg .u64 t; cvta.to.shared.u64 t, %1; cvt.u32.u64 %0, t; }"
        : "=r"(a) : "l"(p));
    return a;
}
__device__ __forceinline__ u64 ffma2(u64 a, u64 b, u64 c) {
    u64 d;
    asm("fma.rn.f32x2 %0, %1, %2, %3;" : "=l"(d) : "l"(a), "l"(b), "l"(c));
    return d;
}
__device__ __forceinline__ u64 fadd2(u64 a, u64 b) {
    u64 d;
    asm("add.rn.f32x2 %0, %1, %2;" : "=l"(d) : "l"(a), "l"(b));
    return d;
}
__device__ __forceinline__ float hadd2(u64 v) {
    float lo, hi;
    asm("mov.b64 {%0,%1}, %2;" : "=f"(lo), "=f"(hi) : "l"(v));
    return lo + hi;
}
// pack: f0 -> low bf16 (memory-first), f1 -> high bf16
__device__ __forceinline__ uint32_t bf16x2_of(float f0, float f1) {
    uint32_t r;
    asm("cvt.rn.bf16x2.f32 %0, %1, %2;" : "=r"(r) : "f"(f1), "f"(f0));
    return r;
}
__device__ __forceinline__ void ldsm_x4(uint32_t* r, uint32_t addr) {
    asm volatile("ldmatrix.sync.aligned.m8n8.x4.shared.b16 {%0,%1,%2,%3}, [%4];"
                 : "=r"(r[0]), "=r"(r[1]), "=r"(r[2]), "=r"(r[3]) : "r"(addr));
}
__device__ __forceinline__ void ldsm_x2(uint32_t* r, uint32_t addr) {
    asm volatile("ldmatrix.sync.aligned.m8n8.x2.shared.b16 {%0,%1}, [%2];"
                 : "=r"(r[0]), "=r"(r[1]) : "r"(addr));
}
__device__ __forceinline__ void mma_bf16(float* d, const uint32_t* a, const uint32_t* b) {
    asm volatile(
        "mma.sync.aligned.m16n8k16.row.col.f32.bf16.bf16.f32 "
        "{%0,%1,%2,%3}, {%4,%5,%6,%7}, {%8,%9}, {%0,%1,%2,%3};"
        : "+f"(d[0]), "+f"(d[1]), "+f"(d[2]), "+f"(d[3])
        : "r"(a[0]), "r"(a[1]), "r"(a[2]), "r"(a[3]), "r"(b[0]), "r"(b[1]));
}
// split f[8] -> hi uint4 + lo uint4 (bf16x2 each)
__device__ __forceinline__ void split8(const float* f, uint4& H, uint4& L) {
    uint32_t hi[4], lo[4];
    #pragma unroll
    for (int q = 0; q < 4; q++) {
        float f0 = f[2 * q], f1 = f[2 * q + 1];
        uint32_t h = bf16x2_of(f0, f1);
        float g0 = __uint_as_float(h << 16);
        float g1 = __uint_as_float(h & 0xffff0000u);
        hi[q] = h;
        lo[q] = bf16x2_of(f0 - g0, f1 - g1);
    }
    H = make_uint4(hi[0], hi[1], hi[2], hi[3]);
    L = make_uint4(lo[0], lo[1], lo[2], lo[3]);
}

__global__ __launch_bounds__(TPB, 3)
void fused_mlp_hmma(const float* __restrict__ sf,
                    const float* __restrict__ W1, const float* __restrict__ b1,
                    const float* __restrict__ W2, const float* __restrict__ b2,
                    const float* __restrict__ Wp, const float* __restrict__ bp,
                    float* __restrict__ out)
{
    extern __shared__ __align__(16) char base[];
    const uint32_t sb = smem_u32(base);

    const int tid  = threadIdx.x;
    const int lane = tid & 31;
    const int w    = tid >> 5;

    // ---- stage W1 pairs + biases ----
    {
        u64* sW1 = (u64*)(base + OFF_W1);
        const u64* g = (const u64*)W1;
        for (int i = tid; i < FC * SF / 2; i += TPB) sW1[i] = g[i];
        if (tid < FC) {
            ((float*)(base + OFF_B1))[tid] = b1[tid];
            ((float*)(base + OFF_B2))[tid] = b2[tid];
            ((float*)(base + OFF_WP))[tid] = Wp[tid];
        }
        if (tid == 0) *((float*)(base + OFF_BP)) = bp[0];
    }

    // ---- stage W2 -> sBh/sBl rows (row j = 64 bf16 k-contiguous) ----
    {
        const int row = tid >> 1, half = tid & 1;   // 32 floats per thread
        const float* src = W2 + row * FC + half * 32;
        #pragma unroll
        for (int g = 0; g < 4; g++) {
            float4 v0 = *(const float4*)(src + g * 8);
            float4 v1 = *(const float4*)(src + g * 8 + 4);
            float f[8] = {v0.x, v0.y, v0.z, v0.w, v1.x, v1.y, v1.z, v1.w};
            uint4 H, L;
            split8(f, H, L);
            const int off = row * STRIDE + half * 64 + g * 16;
            *(uint4*)(base + OFF_BH + off) = H;
            *(uint4*)(base + OFF_BL + off) = L;
        }
    }

    // ---- load static features for this thread's node ----
    const int node = blockIdx.x * NPB + tid;
    u64 s[SF / 2];
    if (node < NN) {
        const ulonglong2* sp = (const ulonglong2*)(sf + (size_t)node * SF);
        ulonglong2 v0 = sp[0], v1 = sp[1], v2 = sp[2];
        s[0] = v0.x; s[1] = v0.y; s[2] = v1.x; s[3] = v1.y; s[4] = v2.x; s[5] = v2.y;
    } else {
        #pragma unroll
        for (int i = 0; i < SF / 2; i++) s[i] = 0ull;
    }
    __syncthreads();   // W1 staged

    // ---- Phase A: h1 row -> split -> sAh/sAl ----
    {
        const u64* sW1 = (const u64*)(base + OFF_W1);
        const float* psb1 = (const float*)(base + OFF_B1);
        #pragma unroll
        for (int gr = 0; gr < 8; gr++) {
            float f[8];
            #pragma unroll
            for (int jj = 0; jj < 8; jj++) {
                const int j = gr * 8 + jj;
                const ulonglong2* wr = (const ulonglong2*)&sW1[j * (SF / 2)];
                ulonglong2 w0 = wr[0], w1 = wr[1], w2 = wr[2];
                u64 a = ffma2(w0.x, s[0], 0ull);
                u64 b = ffma2(w0.y, s[1], 0ull);
                a = ffma2(w1.x, s[2], a);
                b = ffma2(w1.y, s[3], b);
                a = ffma2(w2.x, s[4], a);
                b = ffma2(w2.y, s[5], b);
                f[jj] = fmaxf(hadd2(fadd2(a, b)) + psb1[j], 0.0f);
            }
            uint4 H, L;
            split8(f, H, L);
            const int off = tid * STRIDE + gr * 16;
            *(uint4*)(base + OFF_AH + off) = H;
            *(uint4*)(base + OFF_AL + off) = L;
        }
    }
    __syncthreads();   // A + B tiles ready

    // ---- Phase B: warp-level bf16-split GEMM (M=32/warp, N=64, K=64) ----
    float D[2][8][4];
    #pragma unroll
    for (int mt = 0; mt < 2; mt++)
        #pragma unroll
        for (int n = 0; n < 8; n++)
            #pragma unroll
            for (int q = 0; q < 4; q++) D[mt][n][q] = 0.0f;

    #pragma unroll
    for (int kt = 0; kt < 4; kt++) {
        uint32_t Ah[2][4], Al[2][4];
        #pragma unroll
        for (int mt = 0; mt < 2; mt++) {
            const uint32_t row = w * 32 + mt * 16 + (lane & 15);
            const uint32_t off = row * STRIDE + kt * 32 + ((lane >> 4) << 4);
            ldsm_x4(Ah[mt], sb + OFF_AH + off);
            ldsm_x4(Al[mt], sb + OFF_AL + off);
        }
        #pragma unroll
        for (int n = 0; n < 8; n++) {
            const uint32_t rowb = n * 8 + (lane & 7);
            const uint32_t offb = rowb * STRIDE + kt * 32 + (((lane >> 3) & 1) << 4);
            uint32_t Bh[2], Bl[2];
            ldsm_x2(Bh, sb + OFF_BH + offb);
            ldsm_x2(Bl, sb + OFF_BL + offb);
            #pragma unroll
            for (int mt = 0; mt < 2; mt++) {
                mma_bf16(D[mt][n], Ah[mt], Bh);
                mma_bf16(D[mt][n], Al[mt], Bh);
                mma_bf16(D[mt][n], Ah[mt], Bl);
            }
        }
    }

    // ---- Epilogue: relu + b2, dot with Wp, quad-reduce, store ----
    {
        const float* psb2 = (const float*)(base + OFF_B2);
        const float* pswp = (const float*)(base + OFF_WP);
        const float bps = *((const float*)(base + OFF_BP));

        #pragma unroll
        for (int mt = 0; mt < 2; mt++) {
            float p0 = 0.0f, p1 = 0.0f;
            #pragma unroll
            for (int n = 0; n < 8; n++) {
                const int c = n * 8 + (lane & 3) * 2;
                const float w0 = pswp[c], w1 = pswp[c + 1];
                const float g0 = psb2[c], g1 = psb2[c + 1];
                p0 = fmaf(w0, fmaxf(D[mt][n][0] + g0, 0.0f), p0);
                p0 = fmaf(w1, fmaxf(D[mt][n][1] + g1, 0.0f), p0);
                p1 = fmaf(w0, fmaxf(D[mt][n][2] + g0, 0.0f), p1);
                p1 = fmaf(w1, fmaxf(D[mt][n][3] + g1, 0.0f), p1);
            }
            p0 += __shfl_xor_sync(0xffffffffu, p0, 1);
            p0 += __shfl_xor_sync(0xffffffffu, p0, 2);
            p1 += __shfl_xor_sync(0xffffffffu, p1, 1);
            p1 += __shfl_xor_sync(0xffffffffu, p1, 2);
            if ((lane & 3) == 0) {
                const int r = lane >> 2;
                const int n0 = blockIdx.x * NPB + w * 32 + mt * 16 + r;
                if (n0 < NN)     out[n0]     = p0 + bps;
                if (n0 + 8 < NN) out[n0 + 8] = p1 + bps;
            }
        }
    }
}

extern "C" void kernel_launch(void* const* d_in, const int* in_sizes, int n_in,
                              void* d_out, int out_size)
{
    const float* sf = (const float*)d_in[2];
    const float* W1 = (const float*)d_in[9];
    const float* b1 = (const float*)d_in[10];
    const float* W2 = (const float*)d_in[11];
    const float* b2 = (const float*)d_in[12];
    const float* Wp = (const float*)d_in[13];
    const float* bp = (const float*)d_in[14];
    float* out = (float*)d_out;

    cudaFuncSetAttribute(fused_mlp_hmma,
                         cudaFuncAttributeMaxDynamicSharedMemorySize, SMEM_DYN);
    const int grid = (NN + NPB - 1) / NPB;   // 782
    fused_mlp_hmma<<<grid, TPB, SMEM_DYN>>>(sf, W1, b1, W2, b2, Wp, bp, out);
}

// round 7
// speedup vs baseline: 2.8031x; 1.3743x over previous
#include <cuda_runtime.h>
#include <cuda_bf16.h>
#include <cstdint>

// Live computation (GNN branch is dead code in the reference):
//   h1 = relu(sf @ Wfc1^T + bfc1)     [N,12] -> [N,64]   (HMMA, K padded to 16)
//   h2 = relu(h1 @ Wfc2^T + bfc2)     [N,64] -> [N,64]   (HMMA, A register-chained)
//   out = h2 @ Wp^T + bp              [N,64] -> [N,1]    (register epilogue)
//
// Both layers on mma.sync.m16n8k16 bf16 with 2-way split (D = Ah*Bh + Al*Bh + Ah*Bl).
// Layer-1 A fragments built directly from global loads (no smem);
// layer-1 D fragments ARE layer-2 A fragments (n-tile pair == k-tile identity),
// so h1 never touches shared memory.

#define NN    100000
#define SF    12
#define FC    64
#define TPB   128
#define NPB   128
#define BSTR  144             // W2 smem row stride (bytes): 9x16B, conflict-free
#define WSTR  48              // W1 smem row stride (bytes): 3x16B, conflict-free

using u64 = unsigned long long;

// ---- dynamic smem layout (byte offsets) ----
#define OFF_B2H  0            // 64 x 144
#define OFF_B2L  9216         // 64 x 144
#define OFF_W1H  18432        // 64 x 48
#define OFF_W1L  21504        // 64 x 48
#define OFF_B1   24576        // float[64]
#define OFF_B2   24832        // float[64]
#define OFF_WP   25088        // float[64]
#define OFF_BP   25344        // float
#define SMEM_DYN 25600

__device__ __forceinline__ uint32_t smem_u32(const void* p) {
    uint32_t a;
    asm("{ .reg .u64 t; cvta.to.shared.u64 t, %1; cvt.u32.u64 %0, t; }"
        : "=r"(a) : "l"(p));
    return a;
}
// pack: f0 -> low bf16, f1 -> high bf16
__device__ __forceinline__ uint32_t bf16x2_of(float f0, float f1) {
    uint32_t r;
    asm("cvt.rn.bf16x2.f32 %0, %1, %2;" : "=r"(r) : "f"(f1), "f"(f0));
    return r;
}
__device__ __forceinline__ void split2(float f0, float f1, uint32_t& h, uint32_t& l) {
    h = bf16x2_of(f0, f1);
    float g0 = __uint_as_float(h << 16);
    float g1 = __uint_as_float(h & 0xffff0000u);
    l = bf16x2_of(f0 - g0, f1 - g1);
}
__device__ __forceinline__ void ldsm_x4(uint32_t* r, uint32_t addr) {
    asm volatile("ldmatrix.sync.aligned.m8n8.x4.shared.b16 {%0,%1,%2,%3}, [%4];"
                 : "=r"(r[0]), "=r"(r[1]), "=r"(r[2]), "=r"(r[3]) : "r"(addr));
}
__device__ __forceinline__ void mma_bf16(float* d, const uint32_t* a, const uint32_t* b) {
    asm volatile(
        "mma.sync.aligned.m16n8k16.row.col.f32.bf16.bf16.f32 "
        "{%0,%1,%2,%3}, {%4,%5,%6,%7}, {%8,%9}, {%0,%1,%2,%3};"
        : "+f"(d[0]), "+f"(d[1]), "+f"(d[2]), "+f"(d[3])
        : "r"(a[0]), "r"(a[1]), "r"(a[2]), "r"(a[3]), "r"(b[0]), "r"(b[1]));
}

__global__ __launch_bounds__(TPB)
void fused_mlp_hmma2(const float* __restrict__ sf,
                     const float* __restrict__ W1, const float* __restrict__ b1,
                     const float* __restrict__ W2, const float* __restrict__ b2,
                     const float* __restrict__ Wp, const float* __restrict__ bp,
                     float* __restrict__ out)
{
    extern __shared__ __align__(16) char base[];
    const uint32_t sb = smem_u32(base);

    const int tid  = threadIdx.x;
    const int lane = tid & 31;
    const int w    = tid >> 5;
    const int q    = lane & 3;
    const int r4   = lane >> 2;

    // ---- stage W2 -> B2h/B2l (rows = output j, 64 bf16 k-contig, stride 144) ----
    {
        const int row = tid >> 1, half = tid & 1;
        const float* src = W2 + row * FC + half * 32;
        #pragma unroll
        for (int g = 0; g < 4; g++) {
            float4 v0 = *(const float4*)(src + g * 8);
            float4 v1 = *(const float4*)(src + g * 8 + 4);
            uint32_t h0, l0, h1_, l1_, h2, l2, h3, l3;
            split2(v0.x, v0.y, h0, l0);
            split2(v0.z, v0.w, h1_, l1_);
            split2(v1.x, v1.y, h2, l2);
            split2(v1.z, v1.w, h3, l3);
            const int off = row * BSTR + half * 64 + g * 16;
            *(uint4*)(base + OFF_B2H + off) = make_uint4(h0, h1_, h2, h3);
            *(uint4*)(base + OFF_B2L + off) = make_uint4(l0, l1_, l2, l3);
        }
    }
    // ---- stage W1 -> W1h/W1l (rows = output j, 12 bf16 + 4 zero pad, stride 48) ----
    if (tid < FC) {
        const float* src = W1 + tid * SF;
        float4 v0 = *(const float4*)(src);
        float4 v1 = *(const float4*)(src + 4);
        float4 v2 = *(const float4*)(src + 8);
        uint32_t h0, l0, h1_, l1_, h2, l2, h3, l3, h4, l4, h5, l5;
        split2(v0.x, v0.y, h0, l0);
        split2(v0.z, v0.w, h1_, l1_);
        split2(v1.x, v1.y, h2, l2);
        split2(v1.z, v1.w, h3, l3);
        split2(v2.x, v2.y, h4, l4);
        split2(v2.z, v2.w, h5, l5);
        const int off = tid * WSTR;
        *(uint4*)(base + OFF_W1H + off)      = make_uint4(h0, h1_, h2, h3);
        *(uint4*)(base + OFF_W1H + off + 16) = make_uint4(h4, h5, 0u, 0u);   // kcols 12-15 = 0
        *(uint4*)(base + OFF_W1L + off)      = make_uint4(l0, l1_, l2, l3);
        *(uint4*)(base + OFF_W1L + off + 16) = make_uint4(l4, l5, 0u, 0u);
        ((float*)(base + OFF_B1))[tid] = b1[tid];
        ((float*)(base + OFF_B2))[tid] = b2[tid];
        ((float*)(base + OFF_WP))[tid] = Wp[tid];
    }
    if (tid == 0) *((float*)(base + OFF_BP)) = bp[0];

    // ---- layer-1 A fragments from global (K=16, cols 12-15 zero) ----
    const int nodebase = blockIdx.x * NPB + w * 32;
    uint32_t Ah1[2][4], Al1[2][4];
    #pragma unroll
    for (int mt = 0; mt < 2; mt++) {
        const int row0 = nodebase + mt * 16 + r4;
        const int row1 = row0 + 8;
        float2 v00 = make_float2(0.f, 0.f), v01 = v00, v10 = v00, v11 = v00;
        if (row0 < NN) {
            v00 = *(const float2*)(sf + (size_t)row0 * SF + 2 * q);
            if (q < 2) v01 = *(const float2*)(sf + (size_t)row0 * SF + 2 * q + 8);
        }
        if (row1 < NN) {
            v10 = *(const float2*)(sf + (size_t)row1 * SF + 2 * q);
            if (q < 2) v11 = *(const float2*)(sf + (size_t)row1 * SF + 2 * q + 8);
        }
        split2(v00.x, v00.y, Ah1[mt][0], Al1[mt][0]);
        split2(v10.x, v10.y, Ah1[mt][1], Al1[mt][1]);
        split2(v01.x, v01.y, Ah1[mt][2], Al1[mt][2]);
        split2(v11.x, v11.y, Ah1[mt][3], Al1[mt][3]);
    }
    __syncthreads();   // all smem staged

    // ---- W1 B-fragments (held in registers, 8 n-tiles x hi/lo) ----
    uint32_t B1h[8][2], B1l[8][2];
    {
        const int local = lane & 7, mat = lane >> 3;
        const int kc = mat & 1, ntoff = mat >> 1;
        #pragma unroll
        for (int p = 0; p < 4; p++) {
            const uint32_t roff = ((2 * p + ntoff) * 8 + local) * WSTR + kc * 16;
            uint32_t r[4];
            ldsm_x4(r, sb + OFF_W1H + roff);
            B1h[2 * p][0] = r[0]; B1h[2 * p][1] = r[1];
            B1h[2 * p + 1][0] = r[2]; B1h[2 * p + 1][1] = r[3];
            ldsm_x4(r, sb + OFF_W1L + roff);
            B1l[2 * p][0] = r[0]; B1l[2 * p][1] = r[1];
            B1l[2 * p + 1][0] = r[2]; B1l[2 * p + 1][1] = r[3];
        }
    }

    // ---- layer-1 MMA: D1[2][8][4] ----
    float D1[2][8][4];
    #pragma unroll
    for (int mt = 0; mt < 2; mt++)
        #pragma unroll
        for (int n = 0; n < 8; n++) {
            #pragma unroll
            for (int c = 0; c < 4; c++) D1[mt][n][c] = 0.0f;
            mma_bf16(D1[mt][n], Ah1[mt], B1h[n]);
            mma_bf16(D1[mt][n], Al1[mt], B1h[n]);
            mma_bf16(D1[mt][n], Ah1[mt], B1l[n]);
        }

    // ---- epilogue-1: relu + b1; build layer-2 A fragments (register chain) ----
    // k-tile j of layer-2 A == D1 n-tiles {2j, 2j+1}.
    uint32_t A2h[2][4][4], A2l[2][4][4];
    {
        #pragma unroll
        for (int n = 0; n < 8; n++) {
            const float2 bv = *(const float2*)(base + OFF_B1 + (n * 8 + 2 * q) * 4);
            #pragma unroll
            for (int mt = 0; mt < 2; mt++) {
                D1[mt][n][0] = fmaxf(D1[mt][n][0] + bv.x, 0.0f);
                D1[mt][n][1] = fmaxf(D1[mt][n][1] + bv.y, 0.0f);
                D1[mt][n][2] = fmaxf(D1[mt][n][2] + bv.x, 0.0f);
                D1[mt][n][3] = fmaxf(D1[mt][n][3] + bv.y, 0.0f);
            }
        }
        #pragma unroll
        for (int mt = 0; mt < 2; mt++)
            #pragma unroll
            for (int kt = 0; kt < 4; kt++) {
                split2(D1[mt][2 * kt][0],     D1[mt][2 * kt][1],     A2h[mt][kt][0], A2l[mt][kt][0]);
                split2(D1[mt][2 * kt][2],     D1[mt][2 * kt][3],     A2h[mt][kt][1], A2l[mt][kt][1]);
                split2(D1[mt][2 * kt + 1][0], D1[mt][2 * kt + 1][1], A2h[mt][kt][2], A2l[mt][kt][2]);
                split2(D1[mt][2 * kt + 1][2], D1[mt][2 * kt + 1][3], A2h[mt][kt][3], A2l[mt][kt][3]);
            }
    }

    // ---- layer-2 MMA: D2 = A2h*B2h + A2l*B2h + A2h*B2l ----
    float D2[2][8][4];
    #pragma unroll
    for (int mt = 0; mt < 2; mt++)
        #pragma unroll
        for (int n = 0; n < 8; n++)
            #pragma unroll
            for (int c = 0; c < 4; c++) D2[mt][n][c] = 0.0f;

    {
        const int local = lane & 7, mat = lane >> 3;
        const int kc = mat & 1, ntoff = mat >> 1;
        #pragma unroll
        for (int kt = 0; kt < 4; kt++) {
            #pragma unroll
            for (int p = 0; p < 4; p++) {
                const uint32_t roff = ((2 * p + ntoff) * 8 + local) * BSTR + kt * 32 + kc * 16;
                uint32_t bh[4], bl[4];
                ldsm_x4(bh, sb + OFF_B2H + roff);
                ldsm_x4(bl, sb + OFF_B2L + roff);
                #pragma unroll
                for (int mt = 0; mt < 2; mt++) {
                    mma_bf16(D2[mt][2 * p],     A2h[mt][kt], &bh[0]);
                    mma_bf16(D2[mt][2 * p],     A2l[mt][kt], &bh[0]);
                    mma_bf16(D2[mt][2 * p],     A2h[mt][kt], &bl[0]);
                    mma_bf16(D2[mt][2 * p + 1], A2h[mt][kt], &bh[2]);
                    mma_bf16(D2[mt][2 * p + 1], A2l[mt][kt], &bh[2]);
                    mma_bf16(D2[mt][2 * p + 1], A2h[mt][kt], &bl[2]);
                }
            }
        }
    }

    // ---- epilogue-2: relu + b2, dot with Wp, quad-reduce, store ----
    {
        const float bps = *((const float*)(base + OFF_BP));
        #pragma unroll
        for (int mt = 0; mt < 2; mt++) {
            float p0 = 0.0f, p1 = 0.0f;
            #pragma unroll
            for (int n = 0; n < 8; n++) {
                const float2 g = *(const float2*)(base + OFF_B2 + (n * 8 + 2 * q) * 4);
                const float2 wv = *(const float2*)(base + OFF_WP + (n * 8 + 2 * q) * 4);
                p0 = fmaf(wv.x, fmaxf(D2[mt][n][0] + g.x, 0.0f), p0);
                p0 = fmaf(wv.y, fmaxf(D2[mt][n][1] + g.y, 0.0f), p0);
                p1 = fmaf(wv.x, fmaxf(D2[mt][n][2] + g.x, 0.0f), p1);
                p1 = fmaf(wv.y, fmaxf(D2[mt][n][3] + g.y, 0.0f), p1);
            }
            p0 += __shfl_xor_sync(0xffffffffu, p0, 1);
            p0 += __shfl_xor_sync(0xffffffffu, p0, 2);
            p1 += __shfl_xor_sync(0xffffffffu, p1, 1);
            p1 += __shfl_xor_sync(0xffffffffu, p1, 2);
            if (q == 0) {
                const int n0 = nodebase + mt * 16 + r4;
                if (n0 < NN)     out[n0]     = p0 + bps;
                if (n0 + 8 < NN) out[n0 + 8] = p1 + bps;
            }
        }
    }
}

extern "C" void kernel_launch(void* const* d_in, const int* in_sizes, int n_in,
                              void* d_out, int out_size)
{
    const float* sf = (const float*)d_in[2];
    const float* W1 = (const float*)d_in[9];
    const float* b1 = (const float*)d_in[10];
    const float* W2 = (const float*)d_in[11];
    const float* b2 = (const float*)d_in[12];
    const float* Wp = (const float*)d_in[13];
    const float* bp = (const float*)d_in[14];
    float* out = (float*)d_out;

    cudaFuncSetAttribute(fused_mlp_hmma2,
                         cudaFuncAttributeMaxDynamicSharedMemorySize, SMEM_DYN);
    const int grid = (NN + NPB - 1) / NPB;   // 782
    fused_mlp_hmma2<<<grid, TPB, SMEM_DYN>>>(sf, W1, b1, W2, b2, Wp, bp, out);
}